// round 14
// baseline (speedup 1.0000x reference)
#include <cuda_runtime.h>
#include <cuda_fp16.h>
#include <math.h>
#include <stdint.h>

#define EMBED 1024
#define NHEAD 16
#define HDIM 64
#define SEQ 2048
#define BATCH 2
#define MROWS 4096           // BATCH*SEQ
#define MLPH 4096
#define UNIT (4096u*1024u)   // 4.19M floats

// Scratch (float units): x1 | h | attn | qkv(2U) | mlp(2U) | wh_qkv | wh_proj | wh_fc1 | wh_fc2
__device__ float g_scratch[11u * UNIT];

// ===========================================================================
// Helpers
// ===========================================================================
__device__ __forceinline__ uint32_t smem_u32(const void* p) {
    uint32_t a;
    asm("{ .reg .u64 t; cvta.to.shared.u64 t, %1; cvt.u32.u64 %0, t; }" : "=r"(a) : "l"(p));
    return a;
}
__device__ __forceinline__ void cp_async16(uint32_t smem, const void* g) {
    asm volatile("cp.async.cg.shared.global [%0], [%1], 16;" :: "r"(smem), "l"(g));
}
#define CP_COMMIT() asm volatile("cp.async.commit_group;" ::: "memory")
#define CP_WAIT0()  asm volatile("cp.async.wait_group 0;" ::: "memory")
#define CP_WAIT1()  asm volatile("cp.async.wait_group 1;" ::: "memory")

#define MMA_F16(acc, a, b0, b1)                                               \
    asm volatile(                                                             \
        "mma.sync.aligned.m16n8k16.row.col.f32.f16.f16.f32 "                  \
        "{%0,%1,%2,%3},{%4,%5,%6,%7},{%8,%9},{%0,%1,%2,%3};"                  \
        : "+f"((acc)[0]), "+f"((acc)[1]), "+f"((acc)[2]), "+f"((acc)[3])      \
        : "r"((a)[0]), "r"((a)[1]), "r"((a)[2]), "r"((a)[3]),                 \
          "r"(b0), "r"(b1))

// fp16-accumulator variant: C/D are 2 packed half2 regs
#define MMA_F16ACC(c, a, b0, b1)                                              \
    asm volatile(                                                             \
        "mma.sync.aligned.m16n8k16.row.col.f16.f16.f16.f16 "                  \
        "{%0,%1},{%2,%3,%4,%5},{%6,%7},{%0,%1};"                              \
        : "+r"((c)[0]), "+r"((c)[1])                                          \
        : "r"((a)[0]), "r"((a)[1]), "r"((a)[2]), "r"((a)[3]),                 \
          "r"(b0), "r"(b1))

#define LDSM_X4(r0, r1, r2, r3, addr)                                         \
    asm volatile("ldmatrix.sync.aligned.m8n8.x4.shared.b16 {%0,%1,%2,%3}, [%4];" \
        : "=r"(r0), "=r"(r1), "=r"(r2), "=r"(r3) : "r"(addr))

#define LDSM_X4_TRANS(r0, r1, r2, r3, addr)                                   \
    asm volatile("ldmatrix.sync.aligned.m8n8.x4.trans.shared.b16 {%0,%1,%2,%3}, [%4];" \
        : "=r"(r0), "=r"(r1), "=r"(r2), "=r"(r3) : "r"(addr))

#define EX2_F16X2(d, s)                                                       \
    asm volatile("ex2.approx.f16x2 %0, %1;" : "=r"(d) : "r"(s))

// ===========================================================================
// fp16 mma.sync GEMM:  C[M,N] = A[M,K] @ W   (A [M,K] half; W [K,N] half NATURAL)
// CTA 128x128, BK=64, 256 threads (2x4 warps, 64x32 warp tile), 2-stage dbl buf.
// 16 warps/SM (vs 8) for HMMA latency hiding. LDSM:MMA ratio unchanged.
// ===========================================================================
#define TM 128
#define TN 128
#define BKH 64
#define PH 72
#define PB 136
#define STAGE_H (TM * PH + BKH * PB)   // 17920 halves = 35840 B

extern __shared__ __half gsm_h[];

template<int HASBIAS, int DOGELU, int HASRES, int OUTHALF>
__global__ void __launch_bounds__(256, 2)
hmma_gemm(const __half* __restrict__ A, const __half* __restrict__ W,
          const float* __restrict__ bias, const float* __restrict__ resid,
          void* __restrict__ Cout, int N, int K) {
    const int tid = threadIdx.x;
    const int lane = tid & 31, wid = tid >> 5;
    const int g = lane >> 2, t4 = lane & 3;
    const int wm = wid >> 2, wn = wid & 3;       // 2x4 warps, 64x32 tiles
    const int m0 = blockIdx.y * TM, n0 = blockIdx.x * TN;

    const __half* Ag = A + (size_t)m0 * K;
    const __half* Bg = W + n0;                   // rows stride N

    float acc[4][4][4];
    #pragma unroll
    for (int mi = 0; mi < 4; mi++)
        #pragma unroll
        for (int ni = 0; ni < 4; ni++)
            #pragma unroll
            for (int r = 0; r < 4; r++) acc[mi][ni][r] = 0.f;

    const int NS = K / BKH;

    const int a_row = (lane & 15);
    const int a_col = (lane >> 4) * 8;
    const int v_row = (lane & 7) + ((lane >> 3) & 1) * 8;   // trans-B addressing
    const int v_col = ((lane >> 4) & 1) * 8;

    auto load_stage = [&](int s, int buf) {
        __half* As = gsm_h + buf * STAGE_H;
        __half* Bs = As + TM * PH;
        const __half* Ap = Ag + s * BKH;
        const __half* Bp = Bg + (size_t)(s * BKH) * N;
        #pragma unroll
        for (int i = 0; i < 4; i++) {            // A: 128 rows x 8 slots of 16B
            int op = tid + i * 256;
            int r = op >> 3, sl = op & 7;
            cp_async16(smem_u32(As + r * PH + sl * 8), Ap + (size_t)r * K + sl * 8);
        }
        #pragma unroll
        for (int i = 0; i < 4; i++) {            // B: 64 k-rows x 16 slots of 16B
            int op = tid + i * 256;
            int r = op >> 4, sl = op & 15;
            cp_async16(smem_u32(Bs + r * PB + sl * 8), Bp + (size_t)r * N + sl * 8);
        }
    };

    load_stage(0, 0);
    CP_COMMIT();

    int buf = 0;
    for (int s = 0; s < NS; s++) {
        CP_WAIT0();
        __syncthreads();
        if (s + 1 < NS) { load_stage(s + 1, buf ^ 1); CP_COMMIT(); }

        const __half* As = gsm_h + buf * STAGE_H;
        const __half* Bs = As + TM * PH;

        #pragma unroll
        for (int kk = 0; kk < BKH; kk += 16) {
            uint32_t af[4][4], bf[4][2];
            #pragma unroll
            for (int mi = 0; mi < 4; mi++) {
                uint32_t ad = smem_u32(As + (wm * 64 + mi * 16 + a_row) * PH + kk + a_col);
                LDSM_X4(af[mi][0], af[mi][1], af[mi][2], af[mi][3], ad);
            }
            #pragma unroll
            for (int np = 0; np < 2; np++) {
                uint32_t bd = smem_u32(Bs + (kk + v_row) * PB + wn * 32 + np * 16 + v_col);
                LDSM_X4_TRANS(bf[2*np][0], bf[2*np][1], bf[2*np+1][0], bf[2*np+1][1], bd);
            }
            #pragma unroll
            for (int mi = 0; mi < 4; mi++)
                #pragma unroll
                for (int ni = 0; ni < 4; ni++)
                    MMA_F16(acc[mi][ni], af[mi], bf[ni][0], bf[ni][1]);
        }
        buf ^= 1;
    }

    const float inv_s2 = 0.7071067811865476f;
    #pragma unroll
    for (int ni = 0; ni < 4; ni++) {
        int c = n0 + wn * 32 + ni * 8 + t4 * 2;
        float2 bv = make_float2(0.f, 0.f);
        if (HASBIAS) bv = *(const float2*)(bias + c);
        #pragma unroll
        for (int mi = 0; mi < 4; mi++) {
            int r0 = m0 + wm * 64 + mi * 16 + g;
            #pragma unroll
            for (int h = 0; h < 2; h++) {
                int r = r0 + h * 8;
                float v0 = acc[mi][ni][h * 2 + 0];
                float v1 = acc[mi][ni][h * 2 + 1];
                if (HASBIAS) { v0 += bv.x; v1 += bv.y; }
                if (DOGELU) {
                    v0 = 0.5f * v0 * (1.f + erff(v0 * inv_s2));
                    v1 = 0.5f * v1 * (1.f + erff(v1 * inv_s2));
                }
                if (HASRES) {
                    float2 rd = *(const float2*)(resid + (size_t)r * N + c);
                    v0 += rd.x; v1 += rd.y;
                }
                if (OUTHALF) {
                    *(__half2*)((__half*)Cout + (size_t)r * N + c) =
                        __floats2half2_rn(v0, v1);
                } else {
                    *(float2*)((float*)Cout + (size_t)r * N + c) = make_float2(v0, v1);
                }
            }
        }
    }
}

// ===========================================================================
// Fused weight conversion float -> half for all 4 weight matrices.
// ===========================================================================
#define QKV_N  (1024u*3072u)
#define PROJ_N (1024u*1024u)
#define FC1_N  (1024u*4096u)
#define FC2_N  (4096u*1024u)
#define CONV_TOTAL (QKV_N + PROJ_N + FC1_N + FC2_N)   // 12M

__global__ void conv_all(const float* __restrict__ w_qkv,  __half* __restrict__ o_qkv,
                         const float* __restrict__ w_proj, __half* __restrict__ o_proj,
                         const float* __restrict__ w_fc1,  __half* __restrict__ o_fc1,
                         const float* __restrict__ w_fc2,  __half* __restrict__ o_fc2) {
    size_t i = ((size_t)blockIdx.x * blockDim.x + threadIdx.x) * 8;
    if (i >= CONV_TOTAL) return;
    const float* s;
    __half* d;
    if (i < QKV_N)                        { s = w_qkv  + i;                       d = o_qkv  + i; }
    else if (i < QKV_N + PROJ_N)          { s = w_proj + (i - QKV_N);             d = o_proj + (i - QKV_N); }
    else if (i < QKV_N + PROJ_N + FC1_N)  { s = w_fc1  + (i - QKV_N - PROJ_N);    d = o_fc1  + (i - QKV_N - PROJ_N); }
    else                                  { s = w_fc2  + (i - QKV_N - PROJ_N - FC1_N);
                                            d = o_fc2  + (i - QKV_N - PROJ_N - FC1_N); }
    float4 a = *(const float4*)(s);
    float4 b = *(const float4*)(s + 4);
    __half2 h0 = __floats2half2_rn(a.x, a.y);
    __half2 h1 = __floats2half2_rn(a.z, a.w);
    __half2 h2 = __floats2half2_rn(b.x, b.y);
    __half2 h3 = __floats2half2_rn(b.z, b.w);
    uint4 o;
    o.x = *(uint32_t*)&h0; o.y = *(uint32_t*)&h1;
    o.z = *(uint32_t*)&h2; o.w = *(uint32_t*)&h3;
    *(uint4*)(d) = o;
}

// ===========================================================================
// LayerNorm: float in -> half out. 256 threads x 4 elems = 1024 cols exactly.
// ===========================================================================
__global__ void ln_kernel(const float* __restrict__ x,
                          const float* __restrict__ g,
                          const float* __restrict__ b,
                          __half* __restrict__ out) {
    int row = blockIdx.x;
    const float* xr = x + (size_t)row * EMBED;
    int c = threadIdx.x * 4;
    float4 v = *(const float4*)(xr + c);
    float s  = v.x + v.y + v.z + v.w;
    float s2 = v.x*v.x + v.y*v.y + v.z*v.z + v.w*v.w;
    #pragma unroll
    for (int o = 16; o > 0; o >>= 1) {
        s  += __shfl_xor_sync(0xffffffffu, s,  o);
        s2 += __shfl_xor_sync(0xffffffffu, s2, o);
    }
    __shared__ float red[16];
    int wid = threadIdx.x >> 5, lane = threadIdx.x & 31;
    if (lane == 0) { red[wid] = s; red[wid + 8] = s2; }
    __syncthreads();
    if (threadIdx.x == 0) {
        float ts = 0.f, ts2 = 0.f;
        for (int i = 0; i < 8; i++) { ts += red[i]; ts2 += red[i + 8]; }
        float mu = ts / EMBED;
        red[0] = mu;
        red[1] = rsqrtf(ts2 / EMBED - mu * mu + 1e-5f);
    }
    __syncthreads();
    float mu = red[0], inv = red[1];
    float4 gv = *(const float4*)(g + c);
    float4 bv = *(const float4*)(b + c);
    __half2 h0 = __floats2half2_rn((v.x - mu) * inv * gv.x + bv.x,
                                   (v.y - mu) * inv * gv.y + bv.y);
    __half2 h1 = __floats2half2_rn((v.z - mu) * inv * gv.z + bv.z,
                                   (v.w - mu) * inv * gv.w + bv.w);
    uint2 o;
    o.x = *(uint32_t*)&h0; o.y = *(uint32_t*)&h1;
    *(uint2*)(out + (size_t)row * EMBED + c) = o;
}

// ===========================================================================
// Attention: QK in fp16-accumulator MMA, softmax in packed half2, PV in
// fp32-acc MMA. No running max (scores bounded, fp16 ex2-safe). Streamed
// per-16-key pipeline. Query tile 64, grid 1024 CTAs, 4 CTAs/SM.
// Dyn smem: QP(64)+2x(Ks(64)+Vs(64)) = 46080 B.
// ===========================================================================
#define PA 72
extern __shared__ __half att_hm[];

__global__ void __launch_bounds__(128, 4)
attn_mma(const __half* __restrict__ qkv, __half* __restrict__ out) {
    __half* QP  = att_hm;                 // Q tile [q][d] (dead after frag hoist)
    __half* KV0 = att_hm + 64 * PA;       // buf0: Ks(64) + Vs(64)
    __half* KV1 = att_hm + 192 * PA;      // buf1

    const int qt = blockIdx.x;            // 0..31 (64 queries each)
    const int bh = blockIdx.y;            // 0..31
    const int b = bh >> 4, h = bh & 15;
    const int tid = threadIdx.x, lane = tid & 31, w = tid >> 5;

    const int a_row = (lane & 15);
    const int a_col = (lane >> 4) * 8;
    const int b_row = (lane & 7) + ((lane >> 4) & 1) * 8;
    const int b_col = ((lane >> 3) & 1) * 8;
    const int v_row = (lane & 7) + ((lane >> 3) & 1) * 8;
    const int v_col = ((lane >> 4) & 1) * 8;

    const __half* base = qkv + (size_t)b * SEQ * 3072;
    const int NT = SEQ / 64;

    auto load_kv = [&](int kt, __half* dst) {
        __half* Ks = dst;
        __half* Vs = dst + 64 * PA;
        const __half* Kg = base + (size_t)(kt * 64) * 3072 + 1024 + h * 64;
        const __half* Vg = base + (size_t)(kt * 64) * 3072 + 2048 + h * 64;
        #pragma unroll
        for (int i = 0; i < 4; i++) {
            int op = tid + i * 128;
            int r = op >> 3, sl = op & 7;
            cp_async16(smem_u32(Ks + r * PA + sl * 8), Kg + (size_t)r * 3072 + sl * 8);
        }
        #pragma unroll
        for (int i = 0; i < 4; i++) {
            int op = tid + i * 128;
            int r = op >> 3, sl = op & 7;
            cp_async16(smem_u32(Vs + r * PA + sl * 8), Vg + (size_t)r * 3072 + sl * 8);
        }
    };

    // Q tile (64 rows x 64 halves) + first KV tile
    {
        const __half* Qg = base + (size_t)(qt * 64) * 3072 + h * 64;
        #pragma unroll
        for (int i = 0; i < 4; i++) {
            int op = tid + i * 128;
            int r = op >> 3, sl = op & 7;
            cp_async16(smem_u32(QP + r * PA + sl * 8), Qg + (size_t)r * 3072 + sl * 8);
        }
        CP_COMMIT();
    }
    load_kv(0, KV0);
    CP_COMMIT();
    CP_WAIT0();
    __syncthreads();

    // Hoist Q fragments (kt-invariant): one 16-row m-frag per warp
    uint32_t qf[4][4];
    #pragma unroll
    for (int kf = 0; kf < 4; kf++) {
        uint32_t ad = smem_u32(QP + (w * 16 + a_row) * PA + kf * 16 + a_col);
        LDSM_X4(qf[kf][0], qf[kf][1], qf[kf][2], qf[kf][3], ad);
    }

    float l[2] = {0.f, 0.f};   // row g / row g+8 partials
    float ov[8][4];
    #pragma unroll
    for (int ni = 0; ni < 8; ni++)
        #pragma unroll
        for (int r = 0; r < 4; r++) ov[ni][r] = 0.f;

    const __half2 C1h = __floats2half2_rn(0.18033688011112042f,
                                          0.18033688011112042f);  // 0.125*log2(e)

    int buf = 0;
    for (int kt = 0; kt < NT; kt++) {
        __syncthreads();
        if (kt + 1 < NT) {
            load_kv(kt + 1, buf ? KV0 : KV1);
            CP_COMMIT();
            CP_WAIT1();
        } else {
            CP_WAIT0();
        }
        __syncthreads();

        const __half* Ks = buf ? KV1 : KV0;
        const __half* Vs = Ks + 64 * PA;

        // Streamed per-16-key block: QK(f16 acc) -> exp(half2) -> PV(f32 acc)
        #pragma unroll
        for (int np = 0; np < 4; np++) {
            uint32_t sc[2][2];
            sc[0][0] = 0u; sc[0][1] = 0u; sc[1][0] = 0u; sc[1][1] = 0u;

            #pragma unroll
            for (int kf = 0; kf < 4; kf++) {
                uint32_t b00, b01, b10, b11;
                uint32_t bd = smem_u32(Ks + (np * 16 + b_row) * PA + kf * 16 + b_col);
                LDSM_X4(b00, b01, b10, b11, bd);
                MMA_F16ACC(sc[0], qf[kf], b00, b01);
                MMA_F16ACC(sc[1], qf[kf], b10, b11);
            }

            // P = exp2(C1 * s) in half2; accumulate l partials
            uint32_t pf[4];
            #pragma unroll
            for (int nj = 0; nj < 2; nj++) {
                __half2 tA = __hmul2(*(__half2*)&sc[nj][0], C1h);
                __half2 tB = __hmul2(*(__half2*)&sc[nj][1], C1h);
                uint32_t pA, pB;
                EX2_F16X2(pA, *(uint32_t*)&tA);
                EX2_F16X2(pB, *(uint32_t*)&tB);
                pf[nj * 2 + 0] = pA;
                pf[nj * 2 + 1] = pB;
                float2 fA = __half22float2(*(__half2*)&pA);
                float2 fB = __half22float2(*(__half2*)&pB);
                l[0] += fA.x + fA.y;
                l[1] += fB.x + fB.y;
            }

            // PV k-step for these 16 keys (fp32 accumulators)
            #pragma unroll
            for (int db = 0; db < 4; db++) {
                uint32_t v00, v01, v10, v11;
                uint32_t vd = smem_u32(Vs + (np * 16 + v_row) * PA + db * 16 + v_col);
                LDSM_X4_TRANS(v00, v01, v10, v11, vd);
                MMA_F16(ov[2*db],   pf, v00, v01);
                MMA_F16(ov[2*db+1], pf, v10, v11);
            }
        }
        buf ^= 1;
    }

    // Epilogue: quad-reduce l once, normalize, write half output
    const int g = lane >> 2, t4 = lane & 3;
    float lA = l[0], lB = l[1];
    lA += __shfl_xor_sync(0xffffffffu, lA, 1);
    lA += __shfl_xor_sync(0xffffffffu, lA, 2);
    lB += __shfl_xor_sync(0xffffffffu, lB, 1);
    lB += __shfl_xor_sync(0xffffffffu, lB, 2);
    const float invA = 1.f / lA, invB = 1.f / lB;
    const int qg = b * SEQ + qt * 64 + w * 16 + g;
    #pragma unroll
    for (int ni = 0; ni < 8; ni++) {
        int c = h * 64 + ni * 8 + 2 * t4;
        *(__half2*)(out + (size_t)qg * EMBED + c) =
            __floats2half2_rn(ov[ni][0] * invA, ov[ni][1] * invA);
        *(__half2*)(out + (size_t)(qg + 8) * EMBED + c) =
            __floats2half2_rn(ov[ni][2] * invB, ov[ni][3] * invB);
    }
}

// ===========================================================================
// Host launcher
// ===========================================================================
extern "C" void kernel_launch(void* const* d_in, const int* in_sizes, int n_in,
                              void* d_out, int out_size) {
    const float* x      = (const float*)d_in[0];
    const float* w_qkv  = (const float*)d_in[1];
    const float* w_proj = (const float*)d_in[2];
    const float* b_proj = (const float*)d_in[3];
    const float* w_fc1  = (const float*)d_in[4];
    const float* b_fc1  = (const float*)d_in[5];
    const float* w_fc2  = (const float*)d_in[6];
    const float* b_fc2  = (const float*)d_in[7];
    const float* g1     = (const float*)d_in[8];
    const float* be1    = (const float*)d_in[9];
    const float* g2     = (const float*)d_in[10];
    const float* be2    = (const float*)d_in[11];
    float* out = (float*)d_out;

    void* sp = nullptr;
    cudaGetSymbolAddress(&sp, g_scratch);
    float* scratch = (float*)sp;
    float*  s_x1    = scratch;
    __half* s_h     = (__half*)(scratch + 1ull * UNIT);
    __half* s_attn  = (__half*)(scratch + 2ull * UNIT);
    __half* s_qkv   = (__half*)(scratch + 3ull * UNIT);
    __half* s_mlp   = (__half*)(scratch + 5ull * UNIT);
    __half* wh_qkv  = (__half*)(scratch + 7ull * UNIT);
    __half* wh_proj = (__half*)(scratch + 8ull * UNIT);
    __half* wh_fc1  = (__half*)(scratch + 9ull * UNIT);
    __half* wh_fc2  = (__half*)(scratch + 10ull * UNIT);

    const int ATT_SMEM  = 320 * PA * (int)sizeof(__half);    // 46080
    const int GEMM_SMEM = 2 * STAGE_H * (int)sizeof(__half); // 71680
    cudaFuncSetAttribute(attn_mma, cudaFuncAttributeMaxDynamicSharedMemorySize, ATT_SMEM);
    cudaFuncSetAttribute(hmma_gemm<0,0,0,1>, cudaFuncAttributeMaxDynamicSharedMemorySize, GEMM_SMEM);
    cudaFuncSetAttribute(hmma_gemm<1,0,1,0>, cudaFuncAttributeMaxDynamicSharedMemorySize, GEMM_SMEM);
    cudaFuncSetAttribute(hmma_gemm<1,1,0,1>, cudaFuncAttributeMaxDynamicSharedMemorySize, GEMM_SMEM);

    dim3 t256(256), t128(128);

    // 0. All weight conversions -> half [K,N] (natural layout), one launch
    conv_all<<<(CONV_TOTAL / 8 + 255) / 256, t256>>>(
        w_qkv, wh_qkv, w_proj, wh_proj, w_fc1, wh_fc1, w_fc2, wh_fc2);

    // 1. LN1 -> half
    ln_kernel<<<MROWS, t256>>>(x, g1, be1, s_h);

    // 2. QKV = h @ w_qkv  -> half
    hmma_gemm<0,0,0,1><<<dim3(3072/TN, MROWS/TM), t256, GEMM_SMEM>>>(
        s_h, wh_qkv, nullptr, nullptr, s_qkv, 3072, 1024);

    // 3. Attention -> half (query tile 64, f16-acc QK)
    attn_mma<<<dim3(SEQ / 64, BATCH * NHEAD), t128, ATT_SMEM>>>(s_qkv, s_attn);

    // 4. x1 = x + attn @ w_proj + b_proj  -> float
    hmma_gemm<1,0,1,0><<<dim3(1024/TN, MROWS/TM), t256, GEMM_SMEM>>>(
        s_attn, wh_proj, b_proj, x, s_x1, 1024, 1024);

    // 5. LN2 -> half
    ln_kernel<<<MROWS, t256>>>(s_x1, g2, be2, s_h);

    // 6. mlp = gelu(h2 @ w_fc1 + b_fc1) -> half
    hmma_gemm<1,1,0,1><<<dim3(4096/TN, MROWS/TM), t256, GEMM_SMEM>>>(
        s_h, wh_fc1, b_fc1, nullptr, s_mlp, 4096, 1024);

    // 7. out = x1 + mlp @ w_fc2 + b_fc2  -> float
    hmma_gemm<1,0,1,0><<<dim3(1024/TN, MROWS/TM), t256, GEMM_SMEM>>>(
        s_mlp, wh_fc2, b_fc2, s_x1, out, 1024, 4096);
}

// round 15
// speedup vs baseline: 1.0288x; 1.0288x over previous
#include <cuda_runtime.h>
#include <cuda_fp16.h>
#include <math.h>
#include <stdint.h>

#define EMBED 1024
#define NHEAD 16
#define HDIM 64
#define SEQ 2048
#define BATCH 2
#define MROWS 4096           // BATCH*SEQ
#define MLPH 4096
#define UNIT (4096u*1024u)   // 4.19M floats

// Scratch (float units): x1 | h | attn | qkv(2U) | mlp(2U) | wh_qkv | wh_proj | wh_fc1 | wh_fc2
__device__ float g_scratch[11u * UNIT];

// ===========================================================================
// Helpers
// ===========================================================================
__device__ __forceinline__ uint32_t smem_u32(const void* p) {
    uint32_t a;
    asm("{ .reg .u64 t; cvta.to.shared.u64 t, %1; cvt.u32.u64 %0, t; }" : "=r"(a) : "l"(p));
    return a;
}
__device__ __forceinline__ void cp_async16(uint32_t smem, const void* g) {
    asm volatile("cp.async.cg.shared.global [%0], [%1], 16;" :: "r"(smem), "l"(g));
}
#define CP_COMMIT() asm volatile("cp.async.commit_group;" ::: "memory")
#define CP_WAIT0()  asm volatile("cp.async.wait_group 0;" ::: "memory")
#define CP_WAIT1()  asm volatile("cp.async.wait_group 1;" ::: "memory")

#define MMA_F16(acc, a, b0, b1)                                               \
    asm volatile(                                                             \
        "mma.sync.aligned.m16n8k16.row.col.f32.f16.f16.f32 "                  \
        "{%0,%1,%2,%3},{%4,%5,%6,%7},{%8,%9},{%0,%1,%2,%3};"                  \
        : "+f"((acc)[0]), "+f"((acc)[1]), "+f"((acc)[2]), "+f"((acc)[3])      \
        : "r"((a)[0]), "r"((a)[1]), "r"((a)[2]), "r"((a)[3]),                 \
          "r"(b0), "r"(b1))

// fp16-accumulator variant: C/D are 2 packed half2 regs
#define MMA_F16ACC(c, a, b0, b1)                                              \
    asm volatile(                                                             \
        "mma.sync.aligned.m16n8k16.row.col.f16.f16.f16.f16 "                  \
        "{%0,%1},{%2,%3,%4,%5},{%6,%7},{%0,%1};"                              \
        : "+r"((c)[0]), "+r"((c)[1])                                          \
        : "r"((a)[0]), "r"((a)[1]), "r"((a)[2]), "r"((a)[3]),                 \
          "r"(b0), "r"(b1))

#define LDSM_X4(r0, r1, r2, r3, addr)                                         \
    asm volatile("ldmatrix.sync.aligned.m8n8.x4.shared.b16 {%0,%1,%2,%3}, [%4];" \
        : "=r"(r0), "=r"(r1), "=r"(r2), "=r"(r3) : "r"(addr))

#define LDSM_X4_TRANS(r0, r1, r2, r3, addr)                                   \
    asm volatile("ldmatrix.sync.aligned.m8n8.x4.trans.shared.b16 {%0,%1,%2,%3}, [%4];" \
        : "=r"(r0), "=r"(r1), "=r"(r2), "=r"(r3) : "r"(addr))

#define EX2_F16X2(d, s)                                                       \
    asm volatile("ex2.approx.f16x2 %0, %1;" : "=r"(d) : "r"(s))

// ===========================================================================
// fp16 mma.sync GEMM (R12 proven config):  C[M,N] = A[M,K] @ W (W natural [K,N])
// CTA 128x128, BK=64, 128 threads (2x2 warps, 64x64 warp tile), 2-stage dbl buf.
// ===========================================================================
#define TM 128
#define TN 128
#define BKH 64
#define PH 72
#define PB 136
#define STAGE_H (TM * PH + BKH * PB)   // 17920 halves = 35840 B

extern __shared__ __half gsm_h[];

template<int HASBIAS, int DOGELU, int HASRES, int OUTHALF>
__global__ void __launch_bounds__(128, 2)
hmma_gemm(const __half* __restrict__ A, const __half* __restrict__ W,
          const float* __restrict__ bias, const float* __restrict__ resid,
          void* __restrict__ Cout, int N, int K) {
    const int tid = threadIdx.x;
    const int lane = tid & 31, wid = tid >> 5;
    const int g = lane >> 2, t4 = lane & 3;
    const int wm = wid >> 1, wn = wid & 1;       // 2x2 warps, 64x64 tiles
    const int m0 = blockIdx.y * TM, n0 = blockIdx.x * TN;

    const __half* Ag = A + (size_t)m0 * K;
    const __half* Bg = W + n0;                   // rows stride N

    float acc[4][8][4];
    #pragma unroll
    for (int mi = 0; mi < 4; mi++)
        #pragma unroll
        for (int ni = 0; ni < 8; ni++)
            #pragma unroll
            for (int r = 0; r < 4; r++) acc[mi][ni][r] = 0.f;

    const int NS = K / BKH;

    const int a_row = (lane & 15);
    const int a_col = (lane >> 4) * 8;
    const int v_row = (lane & 7) + ((lane >> 3) & 1) * 8;   // trans-B addressing
    const int v_col = ((lane >> 4) & 1) * 8;

    auto load_stage = [&](int s, int buf) {
        __half* As = gsm_h + buf * STAGE_H;
        __half* Bs = As + TM * PH;
        const __half* Ap = Ag + s * BKH;
        const __half* Bp = Bg + (size_t)(s * BKH) * N;
        #pragma unroll
        for (int i = 0; i < 8; i++) {            // A: 128 rows x 8 slots of 16B
            int op = tid + i * 128;
            int r = op >> 3, sl = op & 7;
            cp_async16(smem_u32(As + r * PH + sl * 8), Ap + (size_t)r * K + sl * 8);
        }
        #pragma unroll
        for (int i = 0; i < 8; i++) {            // B: 64 k-rows x 16 slots of 16B
            int op = tid + i * 128;
            int r = op >> 4, sl = op & 15;
            cp_async16(smem_u32(Bs + r * PB + sl * 8), Bp + (size_t)r * N + sl * 8);
        }
    };

    load_stage(0, 0);
    CP_COMMIT();

    int buf = 0;
    for (int s = 0; s < NS; s++) {
        CP_WAIT0();
        __syncthreads();
        if (s + 1 < NS) { load_stage(s + 1, buf ^ 1); CP_COMMIT(); }

        const __half* As = gsm_h + buf * STAGE_H;
        const __half* Bs = As + TM * PH;

        #pragma unroll
        for (int kk = 0; kk < BKH; kk += 16) {
            uint32_t af[4][4], bf[8][2];
            #pragma unroll
            for (int mi = 0; mi < 4; mi++) {
                uint32_t ad = smem_u32(As + (wm * 64 + mi * 16 + a_row) * PH + kk + a_col);
                LDSM_X4(af[mi][0], af[mi][1], af[mi][2], af[mi][3], ad);
            }
            #pragma unroll
            for (int np = 0; np < 4; np++) {
                uint32_t bd = smem_u32(Bs + (kk + v_row) * PB + wn * 64 + np * 16 + v_col);
                LDSM_X4_TRANS(bf[2*np][0], bf[2*np][1], bf[2*np+1][0], bf[2*np+1][1], bd);
            }
            #pragma unroll
            for (int mi = 0; mi < 4; mi++)
                #pragma unroll
                for (int ni = 0; ni < 8; ni++)
                    MMA_F16(acc[mi][ni], af[mi], bf[ni][0], bf[ni][1]);
        }
        buf ^= 1;
    }

    const float inv_s2 = 0.7071067811865476f;
    #pragma unroll
    for (int ni = 0; ni < 8; ni++) {
        int c = n0 + wn * 64 + ni * 8 + t4 * 2;
        float2 bv = make_float2(0.f, 0.f);
        if (HASBIAS) bv = *(const float2*)(bias + c);
        #pragma unroll
        for (int mi = 0; mi < 4; mi++) {
            int r0 = m0 + wm * 64 + mi * 16 + g;
            #pragma unroll
            for (int h = 0; h < 2; h++) {
                int r = r0 + h * 8;
                float v0 = acc[mi][ni][h * 2 + 0];
                float v1 = acc[mi][ni][h * 2 + 1];
                if (HASBIAS) { v0 += bv.x; v1 += bv.y; }
                if (DOGELU) {
                    v0 = 0.5f * v0 * (1.f + erff(v0 * inv_s2));
                    v1 = 0.5f * v1 * (1.f + erff(v1 * inv_s2));
                }
                if (HASRES) {
                    float2 rd = *(const float2*)(resid + (size_t)r * N + c);
                    v0 += rd.x; v1 += rd.y;
                }
                if (OUTHALF) {
                    *(__half2*)((__half*)Cout + (size_t)r * N + c) =
                        __floats2half2_rn(v0, v1);
                } else {
                    *(float2*)((float*)Cout + (size_t)r * N + c) = make_float2(v0, v1);
                }
            }
        }
    }
}

// ===========================================================================
// Fused weight conversion float -> half for all 4 weight matrices.
// ===========================================================================
#define QKV_N  (1024u*3072u)
#define PROJ_N (1024u*1024u)
#define FC1_N  (1024u*4096u)
#define FC2_N  (4096u*1024u)
#define CONV_TOTAL (QKV_N + PROJ_N + FC1_N + FC2_N)   // 12M

__global__ void conv_all(const float* __restrict__ w_qkv,  __half* __restrict__ o_qkv,
                         const float* __restrict__ w_proj, __half* __restrict__ o_proj,
                         const float* __restrict__ w_fc1,  __half* __restrict__ o_fc1,
                         const float* __restrict__ w_fc2,  __half* __restrict__ o_fc2) {
    size_t i = ((size_t)blockIdx.x * blockDim.x + threadIdx.x) * 8;
    if (i >= CONV_TOTAL) return;
    const float* s;
    __half* d;
    if (i < QKV_N)                        { s = w_qkv  + i;                       d = o_qkv  + i; }
    else if (i < QKV_N + PROJ_N)          { s = w_proj + (i - QKV_N);             d = o_proj + (i - QKV_N); }
    else if (i < QKV_N + PROJ_N + FC1_N)  { s = w_fc1  + (i - QKV_N - PROJ_N);    d = o_fc1  + (i - QKV_N - PROJ_N); }
    else                                  { s = w_fc2  + (i - QKV_N - PROJ_N - FC1_N);
                                            d = o_fc2  + (i - QKV_N - PROJ_N - FC1_N); }
    float4 a = *(const float4*)(s);
    float4 b = *(const float4*)(s + 4);
    __half2 h0 = __floats2half2_rn(a.x, a.y);
    __half2 h1 = __floats2half2_rn(a.z, a.w);
    __half2 h2 = __floats2half2_rn(b.x, b.y);
    __half2 h3 = __floats2half2_rn(b.z, b.w);
    uint4 o;
    o.x = *(uint32_t*)&h0; o.y = *(uint32_t*)&h1;
    o.z = *(uint32_t*)&h2; o.w = *(uint32_t*)&h3;
    *(uint4*)(d) = o;
}

// ===========================================================================
// LayerNorm: float in -> half out. 256 threads x 4 elems = 1024 cols exactly.
// ===========================================================================
__global__ void ln_kernel(const float* __restrict__ x,
                          const float* __restrict__ g,
                          const float* __restrict__ b,
                          __half* __restrict__ out) {
    int row = blockIdx.x;
    const float* xr = x + (size_t)row * EMBED;
    int c = threadIdx.x * 4;
    float4 v = *(const float4*)(xr + c);
    float s  = v.x + v.y + v.z + v.w;
    float s2 = v.x*v.x + v.y*v.y + v.z*v.z + v.w*v.w;
    #pragma unroll
    for (int o = 16; o > 0; o >>= 1) {
        s  += __shfl_xor_sync(0xffffffffu, s,  o);
        s2 += __shfl_xor_sync(0xffffffffu, s2, o);
    }
    __shared__ float red[16];
    int wid = threadIdx.x >> 5, lane = threadIdx.x & 31;
    if (lane == 0) { red[wid] = s; red[wid + 8] = s2; }
    __syncthreads();
    if (threadIdx.x == 0) {
        float ts = 0.f, ts2 = 0.f;
        for (int i = 0; i < 8; i++) { ts += red[i]; ts2 += red[i + 8]; }
        float mu = ts / EMBED;
        red[0] = mu;
        red[1] = rsqrtf(ts2 / EMBED - mu * mu + 1e-5f);
    }
    __syncthreads();
    float mu = red[0], inv = red[1];
    float4 gv = *(const float4*)(g + c);
    float4 bv = *(const float4*)(b + c);
    __half2 h0 = __floats2half2_rn((v.x - mu) * inv * gv.x + bv.x,
                                   (v.y - mu) * inv * gv.y + bv.y);
    __half2 h1 = __floats2half2_rn((v.z - mu) * inv * gv.z + bv.z,
                                   (v.w - mu) * inv * gv.w + bv.w);
    uint2 o;
    o.x = *(uint32_t*)&h0; o.y = *(uint32_t*)&h1;
    *(uint2*)(out + (size_t)row * EMBED + c) = o;
}

// ===========================================================================
// Attention: QK f16-acc MMA, half2 softmax, PV f32-acc MMA, no running max.
// Query tile 64, streamed per-16-key pipeline. Q staging buffer ALIASED onto
// KV1 (Q frags hoisted before KV1's first write; loop-top __syncthreads
// orders hoist vs overwrite). Smem 36864 B; __launch_bounds__(128,5) clamps
// regs to 102 -> 5 CTAs/SM (occ 21% -> 27%).
// ===========================================================================
#define PA 72
extern __shared__ __half att_hm[];

__global__ void __launch_bounds__(128, 5)
attn_mma(const __half* __restrict__ qkv, __half* __restrict__ out) {
    __half* KV0 = att_hm;                 // buf0: Ks(64) + Vs(64)
    __half* KV1 = att_hm + 128 * PA;      // buf1 (also Q staging at prologue)
    __half* QP  = KV1;                    // Q tile [q][d], dead after frag hoist

    const int qt = blockIdx.x;            // 0..31 (64 queries each)
    const int bh = blockIdx.y;            // 0..31
    const int b = bh >> 4, h = bh & 15;
    const int tid = threadIdx.x, lane = tid & 31, w = tid >> 5;

    const int a_row = (lane & 15);
    const int a_col = (lane >> 4) * 8;
    const int b_row = (lane & 7) + ((lane >> 4) & 1) * 8;
    const int b_col = ((lane >> 3) & 1) * 8;
    const int v_row = (lane & 7) + ((lane >> 3) & 1) * 8;
    const int v_col = ((lane >> 4) & 1) * 8;

    const __half* base = qkv + (size_t)b * SEQ * 3072;
    const int NT = SEQ / 64;

    auto load_kv = [&](int kt, __half* dst) {
        __half* Ks = dst;
        __half* Vs = dst + 64 * PA;
        const __half* Kg = base + (size_t)(kt * 64) * 3072 + 1024 + h * 64;
        const __half* Vg = base + (size_t)(kt * 64) * 3072 + 2048 + h * 64;
        #pragma unroll
        for (int i = 0; i < 4; i++) {
            int op = tid + i * 128;
            int r = op >> 3, sl = op & 7;
            cp_async16(smem_u32(Ks + r * PA + sl * 8), Kg + (size_t)r * 3072 + sl * 8);
        }
        #pragma unroll
        for (int i = 0; i < 4; i++) {
            int op = tid + i * 128;
            int r = op >> 3, sl = op & 7;
            cp_async16(smem_u32(Vs + r * PA + sl * 8), Vg + (size_t)r * 3072 + sl * 8);
        }
    };

    // Q tile (into KV1 space) + first KV tile (KV0)
    {
        const __half* Qg = base + (size_t)(qt * 64) * 3072 + h * 64;
        #pragma unroll
        for (int i = 0; i < 4; i++) {
            int op = tid + i * 128;
            int r = op >> 3, sl = op & 7;
            cp_async16(smem_u32(QP + r * PA + sl * 8), Qg + (size_t)r * 3072 + sl * 8);
        }
        CP_COMMIT();
    }
    load_kv(0, KV0);
    CP_COMMIT();
    CP_WAIT0();
    __syncthreads();

    // Hoist Q fragments (kt-invariant) — after this QP/KV1 space is free
    uint32_t qf[4][4];
    #pragma unroll
    for (int kf = 0; kf < 4; kf++) {
        uint32_t ad = smem_u32(QP + (w * 16 + a_row) * PA + kf * 16 + a_col);
        LDSM_X4(qf[kf][0], qf[kf][1], qf[kf][2], qf[kf][3], ad);
    }

    float l[2] = {0.f, 0.f};   // row g / row g+8 partials
    float ov[8][4];
    #pragma unroll
    for (int ni = 0; ni < 8; ni++)
        #pragma unroll
        for (int r = 0; r < 4; r++) ov[ni][r] = 0.f;

    const __half2 C1h = __floats2half2_rn(0.18033688011112042f,
                                          0.18033688011112042f);  // 0.125*log2(e)

    int buf = 0;
    for (int kt = 0; kt < NT; kt++) {
        __syncthreads();   // orders Q-frag hoist (kt=0) / prior reads vs overwrite
        if (kt + 1 < NT) {
            load_kv(kt + 1, buf ? KV0 : KV1);
            CP_COMMIT();
            CP_WAIT1();
        } else {
            CP_WAIT0();
        }
        __syncthreads();

        const __half* Ks = buf ? KV1 : KV0;
        const __half* Vs = Ks + 64 * PA;

        // Streamed per-16-key block: QK(f16 acc) -> exp(half2) -> PV(f32 acc)
        #pragma unroll
        for (int np = 0; np < 4; np++) {
            uint32_t sc[2][2];
            sc[0][0] = 0u; sc[0][1] = 0u; sc[1][0] = 0u; sc[1][1] = 0u;

            #pragma unroll
            for (int kf = 0; kf < 4; kf++) {
                uint32_t b00, b01, b10, b11;
                uint32_t bd = smem_u32(Ks + (np * 16 + b_row) * PA + kf * 16 + b_col);
                LDSM_X4(b00, b01, b10, b11, bd);
                MMA_F16ACC(sc[0], qf[kf], b00, b01);
                MMA_F16ACC(sc[1], qf[kf], b10, b11);
            }

            // P = exp2(C1 * s) in half2; accumulate l partials
            uint32_t pf[4];
            #pragma unroll
            for (int nj = 0; nj < 2; nj++) {
                __half2 tA = __hmul2(*(__half2*)&sc[nj][0], C1h);
                __half2 tB = __hmul2(*(__half2*)&sc[nj][1], C1h);
                uint32_t pA, pB;
                EX2_F16X2(pA, *(uint32_t*)&tA);
                EX2_F16X2(pB, *(uint32_t*)&tB);
                pf[nj * 2 + 0] = pA;
                pf[nj * 2 + 1] = pB;
                float2 fA = __half22float2(*(__half2*)&pA);
                float2 fB = __half22float2(*(__half2*)&pB);
                l[0] += fA.x + fA.y;
                l[1] += fB.x + fB.y;
            }

            // PV k-step for these 16 keys (fp32 accumulators)
            #pragma unroll
            for (int db = 0; db < 4; db++) {
                uint32_t v00, v01, v10, v11;
                uint32_t vd = smem_u32(Vs + (np * 16 + v_row) * PA + db * 16 + v_col);
                LDSM_X4_TRANS(v00, v01, v10, v11, vd);
                MMA_F16(ov[2*db],   pf, v00, v01);
                MMA_F16(ov[2*db+1], pf, v10, v11);
            }
        }
        buf ^= 1;
    }

    // Epilogue: quad-reduce l once, normalize, write half output
    const int g = lane >> 2, t4 = lane & 3;
    float lA = l[0], lB = l[1];
    lA += __shfl_xor_sync(0xffffffffu, lA, 1);
    lA += __shfl_xor_sync(0xffffffffu, lA, 2);
    lB += __shfl_xor_sync(0xffffffffu, lB, 1);
    lB += __shfl_xor_sync(0xffffffffu, lB, 2);
    const float invA = 1.f / lA, invB = 1.f / lB;
    const int qg = b * SEQ + qt * 64 + w * 16 + g;
    #pragma unroll
    for (int ni = 0; ni < 8; ni++) {
        int c = h * 64 + ni * 8 + 2 * t4;
        *(__half2*)(out + (size_t)qg * EMBED + c) =
            __floats2half2_rn(ov[ni][0] * invA, ov[ni][1] * invA);
        *(__half2*)(out + (size_t)(qg + 8) * EMBED + c) =
            __floats2half2_rn(ov[ni][2] * invB, ov[ni][3] * invB);
    }
}

// ===========================================================================
// Host launcher
// ===========================================================================
extern "C" void kernel_launch(void* const* d_in, const int* in_sizes, int n_in,
                              void* d_out, int out_size) {
    const float* x      = (const float*)d_in[0];
    const float* w_qkv  = (const float*)d_in[1];
    const float* w_proj = (const float*)d_in[2];
    const float* b_proj = (const float*)d_in[3];
    const float* w_fc1  = (const float*)d_in[4];
    const float* b_fc1  = (const float*)d_in[5];
    const float* w_fc2  = (const float*)d_in[6];
    const float* b_fc2  = (const float*)d_in[7];
    const float* g1     = (const float*)d_in[8];
    const float* be1    = (const float*)d_in[9];
    const float* g2     = (const float*)d_in[10];
    const float* be2    = (const float*)d_in[11];
    float* out = (float*)d_out;

    void* sp = nullptr;
    cudaGetSymbolAddress(&sp, g_scratch);
    float* scratch = (float*)sp;
    float*  s_x1    = scratch;
    __half* s_h     = (__half*)(scratch + 1ull * UNIT);
    __half* s_attn  = (__half*)(scratch + 2ull * UNIT);
    __half* s_qkv   = (__half*)(scratch + 3ull * UNIT);
    __half* s_mlp   = (__half*)(scratch + 5ull * UNIT);
    __half* wh_qkv  = (__half*)(scratch + 7ull * UNIT);
    __half* wh_proj = (__half*)(scratch + 8ull * UNIT);
    __half* wh_fc1  = (__half*)(scratch + 9ull * UNIT);
    __half* wh_fc2  = (__half*)(scratch + 10ull * UNIT);

    const int ATT_SMEM  = 256 * PA * (int)sizeof(__half);    // 36864
    const int GEMM_SMEM = 2 * STAGE_H * (int)sizeof(__half); // 71680
    cudaFuncSetAttribute(attn_mma, cudaFuncAttributeMaxDynamicSharedMemorySize, ATT_SMEM);
    cudaFuncSetAttribute(hmma_gemm<0,0,0,1>, cudaFuncAttributeMaxDynamicSharedMemorySize, GEMM_SMEM);
    cudaFuncSetAttribute(hmma_gemm<1,0,1,0>, cudaFuncAttributeMaxDynamicSharedMemorySize, GEMM_SMEM);
    cudaFuncSetAttribute(hmma_gemm<1,1,0,1>, cudaFuncAttributeMaxDynamicSharedMemorySize, GEMM_SMEM);

    dim3 t256(256), t128(128);

    // 0. All weight conversions -> half [K,N] (natural layout), one launch
    conv_all<<<(CONV_TOTAL / 8 + 255) / 256, t256>>>(
        w_qkv, wh_qkv, w_proj, wh_proj, w_fc1, wh_fc1, w_fc2, wh_fc2);

    // 1. LN1 -> half
    ln_kernel<<<MROWS, t256>>>(x, g1, be1, s_h);

    // 2. QKV = h @ w_qkv  -> half
    hmma_gemm<0,0,0,1><<<dim3(3072/TN, MROWS/TM), t128, GEMM_SMEM>>>(
        s_h, wh_qkv, nullptr, nullptr, s_qkv, 3072, 1024);

    // 3. Attention -> half (query tile 64, f16-acc QK, 5 CTAs/SM)
    attn_mma<<<dim3(SEQ / 64, BATCH * NHEAD), t128, ATT_SMEM>>>(s_qkv, s_attn);

    // 4. x1 = x + attn @ w_proj + b_proj  -> float
    hmma_gemm<1,0,1,0><<<dim3(1024/TN, MROWS/TM), t128, GEMM_SMEM>>>(
        s_attn, wh_proj, b_proj, x, s_x1, 1024, 1024);

    // 5. LN2 -> half
    ln_kernel<<<MROWS, t256>>>(s_x1, g2, be2, s_h);

    // 6. mlp = gelu(h2 @ w_fc1 + b_fc1) -> half
    hmma_gemm<1,1,0,1><<<dim3(4096/TN, MROWS/TM), t128, GEMM_SMEM>>>(
        s_h, wh_fc1, b_fc1, nullptr, s_mlp, 4096, 1024);

    // 7. out = x1 + mlp @ w_fc2 + b_fc2  -> float
    hmma_gemm<1,0,1,0><<<dim3(1024/TN, MROWS/TM), t128, GEMM_SMEM>>>(
        s_mlp, wh_fc2, b_fc2, s_x1, out, 1024, 4096);
}

// round 16
// speedup vs baseline: 1.0496x; 1.0203x over previous
#include <cuda_runtime.h>
#include <cuda_fp16.h>
#include <math.h>
#include <stdint.h>

#define EMBED 1024
#define NHEAD 16
#define HDIM 64
#define SEQ 2048
#define BATCH 2
#define MROWS 4096           // BATCH*SEQ
#define MLPH 4096
#define UNIT (4096u*1024u)   // 4.19M floats

// Scratch (float units): x1 | h | attn | qkv(2U) | mlp(2U) | wh_qkv | wh_proj | wh_fc1 | wh_fc2
__device__ float g_scratch[11u * UNIT];

// ===========================================================================
// Helpers
// ===========================================================================
__device__ __forceinline__ uint32_t smem_u32(const void* p) {
    uint32_t a;
    asm("{ .reg .u64 t; cvta.to.shared.u64 t, %1; cvt.u32.u64 %0, t; }" : "=r"(a) : "l"(p));
    return a;
}
__device__ __forceinline__ void cp_async16(uint32_t smem, const void* g) {
    asm volatile("cp.async.cg.shared.global [%0], [%1], 16;" :: "r"(smem), "l"(g));
}
#define CP_COMMIT() asm volatile("cp.async.commit_group;" ::: "memory")
#define CP_WAIT0()  asm volatile("cp.async.wait_group 0;" ::: "memory")
#define CP_WAIT1()  asm volatile("cp.async.wait_group 1;" ::: "memory")

#define MMA_F16(acc, a, b0, b1)                                               \
    asm volatile(                                                             \
        "mma.sync.aligned.m16n8k16.row.col.f32.f16.f16.f32 "                  \
        "{%0,%1,%2,%3},{%4,%5,%6,%7},{%8,%9},{%0,%1,%2,%3};"                  \
        : "+f"((acc)[0]), "+f"((acc)[1]), "+f"((acc)[2]), "+f"((acc)[3])      \
        : "r"((a)[0]), "r"((a)[1]), "r"((a)[2]), "r"((a)[3]),                 \
          "r"(b0), "r"(b1))

// fp16-accumulator variant: C/D are 2 packed half2 regs
#define MMA_F16ACC(c, a, b0, b1)                                              \
    asm volatile(                                                             \
        "mma.sync.aligned.m16n8k16.row.col.f16.f16.f16.f16 "                  \
        "{%0,%1},{%2,%3,%4,%5},{%6,%7},{%0,%1};"                              \
        : "+r"((c)[0]), "+r"((c)[1])                                          \
        : "r"((a)[0]), "r"((a)[1]), "r"((a)[2]), "r"((a)[3]),                 \
          "r"(b0), "r"(b1))

#define LDSM_X4(r0, r1, r2, r3, addr)                                         \
    asm volatile("ldmatrix.sync.aligned.m8n8.x4.shared.b16 {%0,%1,%2,%3}, [%4];" \
        : "=r"(r0), "=r"(r1), "=r"(r2), "=r"(r3) : "r"(addr))

#define LDSM_X4_TRANS(r0, r1, r2, r3, addr)                                   \
    asm volatile("ldmatrix.sync.aligned.m8n8.x4.trans.shared.b16 {%0,%1,%2,%3}, [%4];" \
        : "=r"(r0), "=r"(r1), "=r"(r2), "=r"(r3) : "r"(addr))

#define EX2_F16X2(d, s)                                                       \
    asm volatile("ex2.approx.f16x2 %0, %1;" : "=r"(d) : "r"(s))

// ===========================================================================
// fp16 mma.sync GEMM (R12/R13 proven config): C[M,N] = A[M,K] @ W (W [K,N])
// CTA 128x128, BK=64, 128 threads (2x2 warps, 64x64 warp tile), 2-stage dbl buf.
// ===========================================================================
#define TM 128
#define TN 128
#define BKH 64
#define PH 72
#define PB 136
#define STAGE_H (TM * PH + BKH * PB)   // 17920 halves = 35840 B

extern __shared__ __half gsm_h[];

template<int HASBIAS, int DOGELU, int HASRES, int OUTHALF>
__global__ void __launch_bounds__(128, 2)
hmma_gemm(const __half* __restrict__ A, const __half* __restrict__ W,
          const float* __restrict__ bias, const float* __restrict__ resid,
          void* __restrict__ Cout, int N, int K) {
    const int tid = threadIdx.x;
    const int lane = tid & 31, wid = tid >> 5;
    const int g = lane >> 2, t4 = lane & 3;
    const int wm = wid >> 1, wn = wid & 1;       // 2x2 warps, 64x64 tiles
    const int m0 = blockIdx.y * TM, n0 = blockIdx.x * TN;

    const __half* Ag = A + (size_t)m0 * K;
    const __half* Bg = W + n0;                   // rows stride N

    float acc[4][8][4];
    #pragma unroll
    for (int mi = 0; mi < 4; mi++)
        #pragma unroll
        for (int ni = 0; ni < 8; ni++)
            #pragma unroll
            for (int r = 0; r < 4; r++) acc[mi][ni][r] = 0.f;

    const int NS = K / BKH;

    const int a_row = (lane & 15);
    const int a_col = (lane >> 4) * 8;
    const int v_row = (lane & 7) + ((lane >> 3) & 1) * 8;   // trans-B addressing
    const int v_col = ((lane >> 4) & 1) * 8;

    auto load_stage = [&](int s, int buf) {
        __half* As = gsm_h + buf * STAGE_H;
        __half* Bs = As + TM * PH;
        const __half* Ap = Ag + s * BKH;
        const __half* Bp = Bg + (size_t)(s * BKH) * N;
        #pragma unroll
        for (int i = 0; i < 8; i++) {            // A: 128 rows x 8 slots of 16B
            int op = tid + i * 128;
            int r = op >> 3, sl = op & 7;
            cp_async16(smem_u32(As + r * PH + sl * 8), Ap + (size_t)r * K + sl * 8);
        }
        #pragma unroll
        for (int i = 0; i < 8; i++) {            // B: 64 k-rows x 16 slots of 16B
            int op = tid + i * 128;
            int r = op >> 4, sl = op & 15;
            cp_async16(smem_u32(Bs + r * PB + sl * 8), Bp + (size_t)r * N + sl * 8);
        }
    };

    load_stage(0, 0);
    CP_COMMIT();

    int buf = 0;
    for (int s = 0; s < NS; s++) {
        CP_WAIT0();
        __syncthreads();
        if (s + 1 < NS) { load_stage(s + 1, buf ^ 1); CP_COMMIT(); }

        const __half* As = gsm_h + buf * STAGE_H;
        const __half* Bs = As + TM * PH;

        #pragma unroll
        for (int kk = 0; kk < BKH; kk += 16) {
            uint32_t af[4][4], bf[8][2];
            #pragma unroll
            for (int mi = 0; mi < 4; mi++) {
                uint32_t ad = smem_u32(As + (wm * 64 + mi * 16 + a_row) * PH + kk + a_col);
                LDSM_X4(af[mi][0], af[mi][1], af[mi][2], af[mi][3], ad);
            }
            #pragma unroll
            for (int np = 0; np < 4; np++) {
                uint32_t bd = smem_u32(Bs + (kk + v_row) * PB + wn * 64 + np * 16 + v_col);
                LDSM_X4_TRANS(bf[2*np][0], bf[2*np][1], bf[2*np+1][0], bf[2*np+1][1], bd);
            }
            #pragma unroll
            for (int mi = 0; mi < 4; mi++)
                #pragma unroll
                for (int ni = 0; ni < 8; ni++)
                    MMA_F16(acc[mi][ni], af[mi], bf[ni][0], bf[ni][1]);
        }
        buf ^= 1;
    }

    const float inv_s2 = 0.7071067811865476f;
    #pragma unroll
    for (int ni = 0; ni < 8; ni++) {
        int c = n0 + wn * 64 + ni * 8 + t4 * 2;
        float2 bv = make_float2(0.f, 0.f);
        if (HASBIAS) bv = *(const float2*)(bias + c);
        #pragma unroll
        for (int mi = 0; mi < 4; mi++) {
            int r0 = m0 + wm * 64 + mi * 16 + g;
            #pragma unroll
            for (int h = 0; h < 2; h++) {
                int r = r0 + h * 8;
                float v0 = acc[mi][ni][h * 2 + 0];
                float v1 = acc[mi][ni][h * 2 + 1];
                if (HASBIAS) { v0 += bv.x; v1 += bv.y; }
                if (DOGELU) {
                    v0 = 0.5f * v0 * (1.f + erff(v0 * inv_s2));
                    v1 = 0.5f * v1 * (1.f + erff(v1 * inv_s2));
                }
                if (HASRES) {
                    float2 rd = *(const float2*)(resid + (size_t)r * N + c);
                    v0 += rd.x; v1 += rd.y;
                }
                if (OUTHALF) {
                    *(__half2*)((__half*)Cout + (size_t)r * N + c) =
                        __floats2half2_rn(v0, v1);
                } else {
                    *(float2*)((float*)Cout + (size_t)r * N + c) = make_float2(v0, v1);
                }
            }
        }
    }
}

// ===========================================================================
// Fused weight conversion float -> half, 16 floats per thread (higher MLP).
// ===========================================================================
#define QKV_N  (1024u*3072u)
#define PROJ_N (1024u*1024u)
#define FC1_N  (1024u*4096u)
#define FC2_N  (4096u*1024u)
#define CONV_TOTAL (QKV_N + PROJ_N + FC1_N + FC2_N)   // 12M

__global__ void conv_all(const float* __restrict__ w_qkv,  __half* __restrict__ o_qkv,
                         const float* __restrict__ w_proj, __half* __restrict__ o_proj,
                         const float* __restrict__ w_fc1,  __half* __restrict__ o_fc1,
                         const float* __restrict__ w_fc2,  __half* __restrict__ o_fc2) {
    size_t i = ((size_t)blockIdx.x * blockDim.x + threadIdx.x) * 16;
    if (i >= CONV_TOTAL) return;
    // chunk sizes are multiples of 16 so each thread's span stays in one region
    const float* s;
    __half* d;
    if (i < QKV_N)                        { s = w_qkv  + i;                       d = o_qkv  + i; }
    else if (i < QKV_N + PROJ_N)          { s = w_proj + (i - QKV_N);             d = o_proj + (i - QKV_N); }
    else if (i < QKV_N + PROJ_N + FC1_N)  { s = w_fc1  + (i - QKV_N - PROJ_N);    d = o_fc1  + (i - QKV_N - PROJ_N); }
    else                                  { s = w_fc2  + (i - QKV_N - PROJ_N - FC1_N);
                                            d = o_fc2  + (i - QKV_N - PROJ_N - FC1_N); }
    #pragma unroll
    for (int j = 0; j < 2; j++) {
        float4 a = *(const float4*)(s + j * 8);
        float4 b = *(const float4*)(s + j * 8 + 4);
        __half2 h0 = __floats2half2_rn(a.x, a.y);
        __half2 h1 = __floats2half2_rn(a.z, a.w);
        __half2 h2 = __floats2half2_rn(b.x, b.y);
        __half2 h3 = __floats2half2_rn(b.z, b.w);
        uint4 o;
        o.x = *(uint32_t*)&h0; o.y = *(uint32_t*)&h1;
        o.z = *(uint32_t*)&h2; o.w = *(uint32_t*)&h3;
        *(uint4*)(d + j * 8) = o;
    }
}

// ===========================================================================
// LayerNorm: float in -> half out. 256 threads x 4 elems = 1024 cols exactly.
// ===========================================================================
__global__ void ln_kernel(const float* __restrict__ x,
                          const float* __restrict__ g,
                          const float* __restrict__ b,
                          __half* __restrict__ out) {
    int row = blockIdx.x;
    const float* xr = x + (size_t)row * EMBED;
    int c = threadIdx.x * 4;
    float4 v = *(const float4*)(xr + c);
    float s  = v.x + v.y + v.z + v.w;
    float s2 = v.x*v.x + v.y*v.y + v.z*v.z + v.w*v.w;
    #pragma unroll
    for (int o = 16; o > 0; o >>= 1) {
        s  += __shfl_xor_sync(0xffffffffu, s,  o);
        s2 += __shfl_xor_sync(0xffffffffu, s2, o);
    }
    __shared__ float red[16];
    int wid = threadIdx.x >> 5, lane = threadIdx.x & 31;
    if (lane == 0) { red[wid] = s; red[wid + 8] = s2; }
    __syncthreads();
    if (threadIdx.x == 0) {
        float ts = 0.f, ts2 = 0.f;
        for (int i = 0; i < 8; i++) { ts += red[i]; ts2 += red[i + 8]; }
        float mu = ts / EMBED;
        red[0] = mu;
        red[1] = rsqrtf(ts2 / EMBED - mu * mu + 1e-5f);
    }
    __syncthreads();
    float mu = red[0], inv = red[1];
    float4 gv = *(const float4*)(g + c);
    float4 bv = *(const float4*)(b + c);
    __half2 h0 = __floats2half2_rn((v.x - mu) * inv * gv.x + bv.x,
                                   (v.y - mu) * inv * gv.y + bv.y);
    __half2 h1 = __floats2half2_rn((v.z - mu) * inv * gv.z + bv.z,
                                   (v.w - mu) * inv * gv.w + bv.w);
    uint2 o;
    o.x = *(uint32_t*)&h0; o.y = *(uint32_t*)&h1;
    *(uint2*)(out + (size_t)row * EMBED + c) = o;
}

// ===========================================================================
// Attention (R13 best config): QK f16-acc MMA, half2 softmax, PV f32-acc MMA,
// no running max. Query tile 64, streamed per-16-key pipeline, dbl-buf KV.
// __launch_bounds__(128,4), regs ~112, 4 CTAs/SM, smem 46080 B.
// ===========================================================================
#define PA 72
extern __shared__ __half att_hm[];

__global__ void __launch_bounds__(128, 4)
attn_mma(const __half* __restrict__ qkv, __half* __restrict__ out) {
    __half* QP  = att_hm;                 // Q tile [q][d] (dead after frag hoist)
    __half* KV0 = att_hm + 64 * PA;       // buf0: Ks(64) + Vs(64)
    __half* KV1 = att_hm + 192 * PA;      // buf1

    const int qt = blockIdx.x;            // 0..31 (64 queries each)
    const int bh = blockIdx.y;            // 0..31
    const int b = bh >> 4, h = bh & 15;
    const int tid = threadIdx.x, lane = tid & 31, w = tid >> 5;

    const int a_row = (lane & 15);
    const int a_col = (lane >> 4) * 8;
    const int b_row = (lane & 7) + ((lane >> 4) & 1) * 8;
    const int b_col = ((lane >> 3) & 1) * 8;
    const int v_row = (lane & 7) + ((lane >> 3) & 1) * 8;
    const int v_col = ((lane >> 4) & 1) * 8;

    const __half* base = qkv + (size_t)b * SEQ * 3072;
    const int NT = SEQ / 64;

    auto load_kv = [&](int kt, __half* dst) {
        __half* Ks = dst;
        __half* Vs = dst + 64 * PA;
        const __half* Kg = base + (size_t)(kt * 64) * 3072 + 1024 + h * 64;
        const __half* Vg = base + (size_t)(kt * 64) * 3072 + 2048 + h * 64;
        #pragma unroll
        for (int i = 0; i < 4; i++) {
            int op = tid + i * 128;
            int r = op >> 3, sl = op & 7;
            cp_async16(smem_u32(Ks + r * PA + sl * 8), Kg + (size_t)r * 3072 + sl * 8);
        }
        #pragma unroll
        for (int i = 0; i < 4; i++) {
            int op = tid + i * 128;
            int r = op >> 3, sl = op & 7;
            cp_async16(smem_u32(Vs + r * PA + sl * 8), Vg + (size_t)r * 3072 + sl * 8);
        }
    };

    // Q tile (64 rows x 64 halves) + first KV tile
    {
        const __half* Qg = base + (size_t)(qt * 64) * 3072 + h * 64;
        #pragma unroll
        for (int i = 0; i < 4; i++) {
            int op = tid + i * 128;
            int r = op >> 3, sl = op & 7;
            cp_async16(smem_u32(QP + r * PA + sl * 8), Qg + (size_t)r * 3072 + sl * 8);
        }
        CP_COMMIT();
    }
    load_kv(0, KV0);
    CP_COMMIT();
    CP_WAIT0();
    __syncthreads();

    // Hoist Q fragments (kt-invariant): one 16-row m-frag per warp
    uint32_t qf[4][4];
    #pragma unroll
    for (int kf = 0; kf < 4; kf++) {
        uint32_t ad = smem_u32(QP + (w * 16 + a_row) * PA + kf * 16 + a_col);
        LDSM_X4(qf[kf][0], qf[kf][1], qf[kf][2], qf[kf][3], ad);
    }

    float l[2] = {0.f, 0.f};   // row g / row g+8 partials
    float ov[8][4];
    #pragma unroll
    for (int ni = 0; ni < 8; ni++)
        #pragma unroll
        for (int r = 0; r < 4; r++) ov[ni][r] = 0.f;

    const __half2 C1h = __floats2half2_rn(0.18033688011112042f,
                                          0.18033688011112042f);  // 0.125*log2(e)

    int buf = 0;
    for (int kt = 0; kt < NT; kt++) {
        __syncthreads();
        if (kt + 1 < NT) {
            load_kv(kt + 1, buf ? KV0 : KV1);
            CP_COMMIT();
            CP_WAIT1();
        } else {
            CP_WAIT0();
        }
        __syncthreads();

        const __half* Ks = buf ? KV1 : KV0;
        const __half* Vs = Ks + 64 * PA;

        // Streamed per-16-key block: QK(f16 acc) -> exp(half2) -> PV(f32 acc)
        #pragma unroll
        for (int np = 0; np < 4; np++) {
            uint32_t sc[2][2];
            sc[0][0] = 0u; sc[0][1] = 0u; sc[1][0] = 0u; sc[1][1] = 0u;

            #pragma unroll
            for (int kf = 0; kf < 4; kf++) {
                uint32_t b00, b01, b10, b11;
                uint32_t bd = smem_u32(Ks + (np * 16 + b_row) * PA + kf * 16 + b_col);
                LDSM_X4(b00, b01, b10, b11, bd);
                MMA_F16ACC(sc[0], qf[kf], b00, b01);
                MMA_F16ACC(sc[1], qf[kf], b10, b11);
            }

            // P = exp2(C1 * s) in half2; accumulate l partials
            uint32_t pf[4];
            #pragma unroll
            for (int nj = 0; nj < 2; nj++) {
                __half2 tA = __hmul2(*(__half2*)&sc[nj][0], C1h);
                __half2 tB = __hmul2(*(__half2*)&sc[nj][1], C1h);
                uint32_t pA, pB;
                EX2_F16X2(pA, *(uint32_t*)&tA);
                EX2_F16X2(pB, *(uint32_t*)&tB);
                pf[nj * 2 + 0] = pA;
                pf[nj * 2 + 1] = pB;
                float2 fA = __half22float2(*(__half2*)&pA);
                float2 fB = __half22float2(*(__half2*)&pB);
                l[0] += fA.x + fA.y;
                l[1] += fB.x + fB.y;
            }

            // PV k-step for these 16 keys (fp32 accumulators)
            #pragma unroll
            for (int db = 0; db < 4; db++) {
                uint32_t v00, v01, v10, v11;
                uint32_t vd = smem_u32(Vs + (np * 16 + v_row) * PA + db * 16 + v_col);
                LDSM_X4_TRANS(v00, v01, v10, v11, vd);
                MMA_F16(ov[2*db],   pf, v00, v01);
                MMA_F16(ov[2*db+1], pf, v10, v11);
            }
        }
        buf ^= 1;
    }

    // Epilogue: quad-reduce l once, normalize, write half output
    const int g = lane >> 2, t4 = lane & 3;
    float lA = l[0], lB = l[1];
    lA += __shfl_xor_sync(0xffffffffu, lA, 1);
    lA += __shfl_xor_sync(0xffffffffu, lA, 2);
    lB += __shfl_xor_sync(0xffffffffu, lB, 1);
    lB += __shfl_xor_sync(0xffffffffu, lB, 2);
    const float invA = 1.f / lA, invB = 1.f / lB;
    const int qg = b * SEQ + qt * 64 + w * 16 + g;
    #pragma unroll
    for (int ni = 0; ni < 8; ni++) {
        int c = h * 64 + ni * 8 + 2 * t4;
        *(__half2*)(out + (size_t)qg * EMBED + c) =
            __floats2half2_rn(ov[ni][0] * invA, ov[ni][1] * invA);
        *(__half2*)(out + (size_t)(qg + 8) * EMBED + c) =
            __floats2half2_rn(ov[ni][2] * invB, ov[ni][3] * invB);
    }
}

// ===========================================================================
// Host launcher
// ===========================================================================
extern "C" void kernel_launch(void* const* d_in, const int* in_sizes, int n_in,
                              void* d_out, int out_size) {
    const float* x      = (const float*)d_in[0];
    const float* w_qkv  = (const float*)d_in[1];
    const float* w_proj = (const float*)d_in[2];
    const float* b_proj = (const float*)d_in[3];
    const float* w_fc1  = (const float*)d_in[4];
    const float* b_fc1  = (const float*)d_in[5];
    const float* w_fc2  = (const float*)d_in[6];
    const float* b_fc2  = (const float*)d_in[7];
    const float* g1     = (const float*)d_in[8];
    const float* be1    = (const float*)d_in[9];
    const float* g2     = (const float*)d_in[10];
    const float* be2    = (const float*)d_in[11];
    float* out = (float*)d_out;

    void* sp = nullptr;
    cudaGetSymbolAddress(&sp, g_scratch);
    float* scratch = (float*)sp;
    float*  s_x1    = scratch;
    __half* s_h     = (__half*)(scratch + 1ull * UNIT);
    __half* s_attn  = (__half*)(scratch + 2ull * UNIT);
    __half* s_qkv   = (__half*)(scratch + 3ull * UNIT);
    __half* s_mlp   = (__half*)(scratch + 5ull * UNIT);
    __half* wh_qkv  = (__half*)(scratch + 7ull * UNIT);
    __half* wh_proj = (__half*)(scratch + 8ull * UNIT);
    __half* wh_fc1  = (__half*)(scratch + 9ull * UNIT);
    __half* wh_fc2  = (__half*)(scratch + 10ull * UNIT);

    const int ATT_SMEM  = 320 * PA * (int)sizeof(__half);    // 46080
    const int GEMM_SMEM = 2 * STAGE_H * (int)sizeof(__half); // 71680
    cudaFuncSetAttribute(attn_mma, cudaFuncAttributeMaxDynamicSharedMemorySize, ATT_SMEM);
    cudaFuncSetAttribute(hmma_gemm<0,0,0,1>, cudaFuncAttributeMaxDynamicSharedMemorySize, GEMM_SMEM);
    cudaFuncSetAttribute(hmma_gemm<1,0,1,0>, cudaFuncAttributeMaxDynamicSharedMemorySize, GEMM_SMEM);
    cudaFuncSetAttribute(hmma_gemm<1,1,0,1>, cudaFuncAttributeMaxDynamicSharedMemorySize, GEMM_SMEM);

    dim3 t256(256), t128(128);

    // 0. All weight conversions -> half [K,N] (natural layout), one launch
    conv_all<<<(CONV_TOTAL / 16 + 255) / 256, t256>>>(
        w_qkv, wh_qkv, w_proj, wh_proj, w_fc1, wh_fc1, w_fc2, wh_fc2);

    // 1. LN1 -> half
    ln_kernel<<<MROWS, t256>>>(x, g1, be1, s_h);

    // 2. QKV = h @ w_qkv  -> half
    hmma_gemm<0,0,0,1><<<dim3(3072/TN, MROWS/TM), t128, GEMM_SMEM>>>(
        s_h, wh_qkv, nullptr, nullptr, s_qkv, 3072, 1024);

    // 3. Attention -> half (query tile 64, f16-acc QK, 4 CTAs/SM)
    attn_mma<<<dim3(SEQ / 64, BATCH * NHEAD), t128, ATT_SMEM>>>(s_qkv, s_attn);

    // 4. x1 = x + attn @ w_proj + b_proj  -> float
    hmma_gemm<1,0,1,0><<<dim3(1024/TN, MROWS/TM), t128, GEMM_SMEM>>>(
        s_attn, wh_proj, b_proj, x, s_x1, 1024, 1024);

    // 5. LN2 -> half
    ln_kernel<<<MROWS, t256>>>(s_x1, g2, be2, s_h);

    // 6. mlp = gelu(h2 @ w_fc1 + b_fc1) -> half
    hmma_gemm<1,1,0,1><<<dim3(4096/TN, MROWS/TM), t128, GEMM_SMEM>>>(
        s_h, wh_fc1, b_fc1, nullptr, s_mlp, 4096, 1024);

    // 7. out = x1 + mlp @ w_fc2 + b_fc2  -> float
    hmma_gemm<1,0,1,0><<<dim3(1024/TN, MROWS/TM), t128, GEMM_SMEM>>>(
        s_mlp, wh_fc2, b_fc2, s_x1, out, 1024, 4096);
}

// round 17
// speedup vs baseline: 1.0590x; 1.0090x over previous
#include <cuda_runtime.h>
#include <cuda_fp16.h>
#include <math.h>
#include <stdint.h>

#define EMBED 1024
#define NHEAD 16
#define HDIM 64
#define SEQ 2048
#define BATCH 2
#define MROWS 4096           // BATCH*SEQ
#define MLPH 4096
#define UNIT (4096u*1024u)   // 4.19M floats

// Scratch (float units): x1 | h | attn | qkv(2U) | mlp(2U) | wh_qkv | wh_proj | wh_fc1 | wh_fc2
__device__ float g_scratch[11u * UNIT];

// ===========================================================================
// Helpers
// ===========================================================================
__device__ __forceinline__ uint32_t smem_u32(const void* p) {
    uint32_t a;
    asm("{ .reg .u64 t; cvta.to.shared.u64 t, %1; cvt.u32.u64 %0, t; }" : "=r"(a) : "l"(p));
    return a;
}
__device__ __forceinline__ void cp_async16(uint32_t smem, const void* g) {
    asm volatile("cp.async.cg.shared.global [%0], [%1], 16;" :: "r"(smem), "l"(g));
}
#define CP_COMMIT() asm volatile("cp.async.commit_group;" ::: "memory")
#define CP_WAIT0()  asm volatile("cp.async.wait_group 0;" ::: "memory")
#define CP_WAIT1()  asm volatile("cp.async.wait_group 1;" ::: "memory")

#define MMA_F16(acc, a, b0, b1)                                               \
    asm volatile(                                                             \
        "mma.sync.aligned.m16n8k16.row.col.f32.f16.f16.f32 "                  \
        "{%0,%1,%2,%3},{%4,%5,%6,%7},{%8,%9},{%0,%1,%2,%3};"                  \
        : "+f"((acc)[0]), "+f"((acc)[1]), "+f"((acc)[2]), "+f"((acc)[3])      \
        : "r"((a)[0]), "r"((a)[1]), "r"((a)[2]), "r"((a)[3]),                 \
          "r"(b0), "r"(b1))

// fp16-accumulator variant: C/D are 2 packed half2 regs
#define MMA_F16ACC(c, a, b0, b1)                                              \
    asm volatile(                                                             \
        "mma.sync.aligned.m16n8k16.row.col.f16.f16.f16.f16 "                  \
        "{%0,%1},{%2,%3,%4,%5},{%6,%7},{%0,%1};"                              \
        : "+r"((c)[0]), "+r"((c)[1])                                          \
        : "r"((a)[0]), "r"((a)[1]), "r"((a)[2]), "r"((a)[3]),                 \
          "r"(b0), "r"(b1))

#define LDSM_X4(r0, r1, r2, r3, addr)                                         \
    asm volatile("ldmatrix.sync.aligned.m8n8.x4.shared.b16 {%0,%1,%2,%3}, [%4];" \
        : "=r"(r0), "=r"(r1), "=r"(r2), "=r"(r3) : "r"(addr))

#define LDSM_X4_TRANS(r0, r1, r2, r3, addr)                                   \
    asm volatile("ldmatrix.sync.aligned.m8n8.x4.trans.shared.b16 {%0,%1,%2,%3}, [%4];" \
        : "=r"(r0), "=r"(r1), "=r"(r2), "=r"(r3) : "r"(addr))

#define EX2_F16X2(d, s)                                                       \
    asm volatile("ex2.approx.f16x2 %0, %1;" : "=r"(d) : "r"(s))

// ===========================================================================
// fp16 mma.sync GEMM (proven config): C[M,N] = A[M,K] @ W (W natural [K,N])
// CTA 128x128, BK=64, 128 threads (2x2 warps, 64x64 warp tile), 2-stage dbl buf.
// ===========================================================================
#define TM 128
#define TN 128
#define BKH 64
#define PH 72
#define PB 136
#define STAGE_H (TM * PH + BKH * PB)   // 17920 halves = 35840 B

extern __shared__ __half gsm_h[];

template<int HASBIAS, int DOGELU, int HASRES, int OUTHALF>
__global__ void __launch_bounds__(128, 2)
hmma_gemm(const __half* __restrict__ A, const __half* __restrict__ W,
          const float* __restrict__ bias, const float* __restrict__ resid,
          void* __restrict__ Cout, int N, int K) {
    const int tid = threadIdx.x;
    const int lane = tid & 31, wid = tid >> 5;
    const int g = lane >> 2, t4 = lane & 3;
    const int wm = wid >> 1, wn = wid & 1;       // 2x2 warps, 64x64 tiles
    const int m0 = blockIdx.y * TM, n0 = blockIdx.x * TN;

    const __half* Ag = A + (size_t)m0 * K;
    const __half* Bg = W + n0;                   // rows stride N

    float acc[4][8][4];
    #pragma unroll
    for (int mi = 0; mi < 4; mi++)
        #pragma unroll
        for (int ni = 0; ni < 8; ni++)
            #pragma unroll
            for (int r = 0; r < 4; r++) acc[mi][ni][r] = 0.f;

    const int NS = K / BKH;

    const int a_row = (lane & 15);
    const int a_col = (lane >> 4) * 8;
    const int v_row = (lane & 7) + ((lane >> 3) & 1) * 8;   // trans-B addressing
    const int v_col = ((lane >> 4) & 1) * 8;

    auto load_stage = [&](int s, int buf) {
        __half* As = gsm_h + buf * STAGE_H;
        __half* Bs = As + TM * PH;
        const __half* Ap = Ag + s * BKH;
        const __half* Bp = Bg + (size_t)(s * BKH) * N;
        #pragma unroll
        for (int i = 0; i < 8; i++) {            // A: 128 rows x 8 slots of 16B
            int op = tid + i * 128;
            int r = op >> 3, sl = op & 7;
            cp_async16(smem_u32(As + r * PH + sl * 8), Ap + (size_t)r * K + sl * 8);
        }
        #pragma unroll
        for (int i = 0; i < 8; i++) {            // B: 64 k-rows x 16 slots of 16B
            int op = tid + i * 128;
            int r = op >> 4, sl = op & 15;
            cp_async16(smem_u32(Bs + r * PB + sl * 8), Bp + (size_t)r * N + sl * 8);
        }
    };

    load_stage(0, 0);
    CP_COMMIT();

    int buf = 0;
    for (int s = 0; s < NS; s++) {
        CP_WAIT0();
        __syncthreads();
        if (s + 1 < NS) { load_stage(s + 1, buf ^ 1); CP_COMMIT(); }

        const __half* As = gsm_h + buf * STAGE_H;
        const __half* Bs = As + TM * PH;

        #pragma unroll
        for (int kk = 0; kk < BKH; kk += 16) {
            uint32_t af[4][4], bf[8][2];
            #pragma unroll
            for (int mi = 0; mi < 4; mi++) {
                uint32_t ad = smem_u32(As + (wm * 64 + mi * 16 + a_row) * PH + kk + a_col);
                LDSM_X4(af[mi][0], af[mi][1], af[mi][2], af[mi][3], ad);
            }
            #pragma unroll
            for (int np = 0; np < 4; np++) {
                uint32_t bd = smem_u32(Bs + (kk + v_row) * PB + wn * 64 + np * 16 + v_col);
                LDSM_X4_TRANS(bf[2*np][0], bf[2*np][1], bf[2*np+1][0], bf[2*np+1][1], bd);
            }
            #pragma unroll
            for (int mi = 0; mi < 4; mi++)
                #pragma unroll
                for (int ni = 0; ni < 8; ni++)
                    MMA_F16(acc[mi][ni], af[mi], bf[ni][0], bf[ni][1]);
        }
        buf ^= 1;
    }

    const float inv_s2 = 0.7071067811865476f;
    #pragma unroll
    for (int ni = 0; ni < 8; ni++) {
        int c = n0 + wn * 64 + ni * 8 + t4 * 2;
        float2 bv = make_float2(0.f, 0.f);
        if (HASBIAS) bv = *(const float2*)(bias + c);
        #pragma unroll
        for (int mi = 0; mi < 4; mi++) {
            int r0 = m0 + wm * 64 + mi * 16 + g;
            #pragma unroll
            for (int h = 0; h < 2; h++) {
                int r = r0 + h * 8;
                float v0 = acc[mi][ni][h * 2 + 0];
                float v1 = acc[mi][ni][h * 2 + 1];
                if (HASBIAS) { v0 += bv.x; v1 += bv.y; }
                if (DOGELU) {
                    v0 = 0.5f * v0 * (1.f + erff(v0 * inv_s2));
                    v1 = 0.5f * v1 * (1.f + erff(v1 * inv_s2));
                }
                if (HASRES) {
                    float2 rd = *(const float2*)(resid + (size_t)r * N + c);
                    v0 += rd.x; v1 += rd.y;
                }
                if (OUTHALF) {
                    *(__half2*)((__half*)Cout + (size_t)r * N + c) =
                        __floats2half2_rn(v0, v1);
                } else {
                    *(float2*)((float*)Cout + (size_t)r * N + c) = make_float2(v0, v1);
                }
            }
        }
    }
}

// ===========================================================================
// Fused weight conversion float -> half, 16 floats per thread.
// ===========================================================================
#define QKV_N  (1024u*3072u)
#define PROJ_N (1024u*1024u)
#define FC1_N  (1024u*4096u)
#define FC2_N  (4096u*1024u)
#define CONV_TOTAL (QKV_N + PROJ_N + FC1_N + FC2_N)   // 12M

__global__ void conv_all(const float* __restrict__ w_qkv,  __half* __restrict__ o_qkv,
                         const float* __restrict__ w_proj, __half* __restrict__ o_proj,
                         const float* __restrict__ w_fc1,  __half* __restrict__ o_fc1,
                         const float* __restrict__ w_fc2,  __half* __restrict__ o_fc2) {
    size_t i = ((size_t)blockIdx.x * blockDim.x + threadIdx.x) * 16;
    if (i >= CONV_TOTAL) return;
    const float* s;
    __half* d;
    if (i < QKV_N)                        { s = w_qkv  + i;                       d = o_qkv  + i; }
    else if (i < QKV_N + PROJ_N)          { s = w_proj + (i - QKV_N);             d = o_proj + (i - QKV_N); }
    else if (i < QKV_N + PROJ_N + FC1_N)  { s = w_fc1  + (i - QKV_N - PROJ_N);    d = o_fc1  + (i - QKV_N - PROJ_N); }
    else                                  { s = w_fc2  + (i - QKV_N - PROJ_N - FC1_N);
                                            d = o_fc2  + (i - QKV_N - PROJ_N - FC1_N); }
    #pragma unroll
    for (int j = 0; j < 2; j++) {
        float4 a = *(const float4*)(s + j * 8);
        float4 b = *(const float4*)(s + j * 8 + 4);
        __half2 h0 = __floats2half2_rn(a.x, a.y);
        __half2 h1 = __floats2half2_rn(a.z, a.w);
        __half2 h2 = __floats2half2_rn(b.x, b.y);
        __half2 h3 = __floats2half2_rn(b.z, b.w);
        uint4 o;
        o.x = *(uint32_t*)&h0; o.y = *(uint32_t*)&h1;
        o.z = *(uint32_t*)&h2; o.w = *(uint32_t*)&h3;
        *(uint4*)(d + j * 8) = o;
    }
}

// ===========================================================================
// LayerNorm: float in -> half out. 256 threads x 4 elems = 1024 cols exactly.
// ===========================================================================
__global__ void ln_kernel(const float* __restrict__ x,
                          const float* __restrict__ g,
                          const float* __restrict__ b,
                          __half* __restrict__ out) {
    int row = blockIdx.x;
    const float* xr = x + (size_t)row * EMBED;
    int c = threadIdx.x * 4;
    float4 v = *(const float4*)(xr + c);
    float s  = v.x + v.y + v.z + v.w;
    float s2 = v.x*v.x + v.y*v.y + v.z*v.z + v.w*v.w;
    #pragma unroll
    for (int o = 16; o > 0; o >>= 1) {
        s  += __shfl_xor_sync(0xffffffffu, s,  o);
        s2 += __shfl_xor_sync(0xffffffffu, s2, o);
    }
    __shared__ float red[16];
    int wid = threadIdx.x >> 5, lane = threadIdx.x & 31;
    if (lane == 0) { red[wid] = s; red[wid + 8] = s2; }
    __syncthreads();
    if (threadIdx.x == 0) {
        float ts = 0.f, ts2 = 0.f;
        for (int i = 0; i < 8; i++) { ts += red[i]; ts2 += red[i + 8]; }
        float mu = ts / EMBED;
        red[0] = mu;
        red[1] = rsqrtf(ts2 / EMBED - mu * mu + 1e-5f);
    }
    __syncthreads();
    float mu = red[0], inv = red[1];
    float4 gv = *(const float4*)(g + c);
    float4 bv = *(const float4*)(b + c);
    __half2 h0 = __floats2half2_rn((v.x - mu) * inv * gv.x + bv.x,
                                   (v.y - mu) * inv * gv.y + bv.y);
    __half2 h1 = __floats2half2_rn((v.z - mu) * inv * gv.z + bv.z,
                                   (v.w - mu) * inv * gv.w + bv.w);
    uint2 o;
    o.x = *(uint32_t*)&h0; o.y = *(uint32_t*)&h1;
    *(uint2*)(out + (size_t)row * EMBED + c) = o;
}

// ===========================================================================
// Attention (best config + half2 l-accumulation): QK f16-acc MMA, half2
// softmax with per-np half2 partial sums, PV f32-acc MMA, no running max.
// Query tile 64, streamed per-16-key pipeline, dbl-buf KV, 4 CTAs/SM.
// ===========================================================================
#define PA 72
extern __shared__ __half att_hm[];

__global__ void __launch_bounds__(128, 4)
attn_mma(const __half* __restrict__ qkv, __half* __restrict__ out) {
    __half* QP  = att_hm;                 // Q tile [q][d] (dead after frag hoist)
    __half* KV0 = att_hm + 64 * PA;       // buf0: Ks(64) + Vs(64)
    __half* KV1 = att_hm + 192 * PA;      // buf1

    const int qt = blockIdx.x;            // 0..31 (64 queries each)
    const int bh = blockIdx.y;            // 0..31
    const int b = bh >> 4, h = bh & 15;
    const int tid = threadIdx.x, lane = tid & 31, w = tid >> 5;

    const int a_row = (lane & 15);
    const int a_col = (lane >> 4) * 8;
    const int b_row = (lane & 7) + ((lane >> 4) & 1) * 8;
    const int b_col = ((lane >> 3) & 1) * 8;
    const int v_row = (lane & 7) + ((lane >> 3) & 1) * 8;
    const int v_col = ((lane >> 4) & 1) * 8;

    const __half* base = qkv + (size_t)b * SEQ * 3072;
    const int NT = SEQ / 64;

    auto load_kv = [&](int kt, __half* dst) {
        __half* Ks = dst;
        __half* Vs = dst + 64 * PA;
        const __half* Kg = base + (size_t)(kt * 64) * 3072 + 1024 + h * 64;
        const __half* Vg = base + (size_t)(kt * 64) * 3072 + 2048 + h * 64;
        #pragma unroll
        for (int i = 0; i < 4; i++) {
            int op = tid + i * 128;
            int r = op >> 3, sl = op & 7;
            cp_async16(smem_u32(Ks + r * PA + sl * 8), Kg + (size_t)r * 3072 + sl * 8);
        }
        #pragma unroll
        for (int i = 0; i < 4; i++) {
            int op = tid + i * 128;
            int r = op >> 3, sl = op & 7;
            cp_async16(smem_u32(Vs + r * PA + sl * 8), Vg + (size_t)r * 3072 + sl * 8);
        }
    };

    // Q tile (64 rows x 64 halves) + first KV tile
    {
        const __half* Qg = base + (size_t)(qt * 64) * 3072 + h * 64;
        #pragma unroll
        for (int i = 0; i < 4; i++) {
            int op = tid + i * 128;
            int r = op >> 3, sl = op & 7;
            cp_async16(smem_u32(QP + r * PA + sl * 8), Qg + (size_t)r * 3072 + sl * 8);
        }
        CP_COMMIT();
    }
    load_kv(0, KV0);
    CP_COMMIT();
    CP_WAIT0();
    __syncthreads();

    // Hoist Q fragments (kt-invariant): one 16-row m-frag per warp
    uint32_t qf[4][4];
    #pragma unroll
    for (int kf = 0; kf < 4; kf++) {
        uint32_t ad = smem_u32(QP + (w * 16 + a_row) * PA + kf * 16 + a_col);
        LDSM_X4(qf[kf][0], qf[kf][1], qf[kf][2], qf[kf][3], ad);
    }

    float l[2] = {0.f, 0.f};   // row g / row g+8 partials
    float ov[8][4];
    #pragma unroll
    for (int ni = 0; ni < 8; ni++)
        #pragma unroll
        for (int r = 0; r < 4; r++) ov[ni][r] = 0.f;

    const __half2 C1h = __floats2half2_rn(0.18033688011112042f,
                                          0.18033688011112042f);  // 0.125*log2(e)

    int buf = 0;
    for (int kt = 0; kt < NT; kt++) {
        __syncthreads();
        if (kt + 1 < NT) {
            load_kv(kt + 1, buf ? KV0 : KV1);
            CP_COMMIT();
            CP_WAIT1();
        } else {
            CP_WAIT0();
        }
        __syncthreads();

        const __half* Ks = buf ? KV1 : KV0;
        const __half* Vs = Ks + 64 * PA;

        // Streamed per-16-key block: QK(f16 acc) -> exp(half2) -> PV(f32 acc)
        #pragma unroll
        for (int np = 0; np < 4; np++) {
            uint32_t sc[2][2];
            sc[0][0] = 0u; sc[0][1] = 0u; sc[1][0] = 0u; sc[1][1] = 0u;

            #pragma unroll
            for (int kf = 0; kf < 4; kf++) {
                uint32_t b00, b01, b10, b11;
                uint32_t bd = smem_u32(Ks + (np * 16 + b_row) * PA + kf * 16 + b_col);
                LDSM_X4(b00, b01, b10, b11, bd);
                MMA_F16ACC(sc[0], qf[kf], b00, b01);
                MMA_F16ACC(sc[1], qf[kf], b10, b11);
            }

            // P = exp2(C1 * s) in half2; half2 partial sums, one convert per np
            uint32_t pf[4];
            __half2 ps0 = __floats2half2_rn(0.f, 0.f);
            __half2 ps1 = __floats2half2_rn(0.f, 0.f);
            #pragma unroll
            for (int nj = 0; nj < 2; nj++) {
                __half2 tA = __hmul2(*(__half2*)&sc[nj][0], C1h);
                __half2 tB = __hmul2(*(__half2*)&sc[nj][1], C1h);
                uint32_t pA, pB;
                EX2_F16X2(pA, *(uint32_t*)&tA);
                EX2_F16X2(pB, *(uint32_t*)&tB);
                pf[nj * 2 + 0] = pA;
                pf[nj * 2 + 1] = pB;
                ps0 = __hadd2(ps0, *(__half2*)&pA);
                ps1 = __hadd2(ps1, *(__half2*)&pB);
            }
            float2 f0 = __half22float2(ps0);
            float2 f1 = __half22float2(ps1);
            l[0] += f0.x + f0.y;
            l[1] += f1.x + f1.y;

            // PV k-step for these 16 keys (fp32 accumulators)
            #pragma unroll
            for (int db = 0; db < 4; db++) {
                uint32_t v00, v01, v10, v11;
                uint32_t vd = smem_u32(Vs + (np * 16 + v_row) * PA + db * 16 + v_col);
                LDSM_X4_TRANS(v00, v01, v10, v11, vd);
                MMA_F16(ov[2*db],   pf, v00, v01);
                MMA_F16(ov[2*db+1], pf, v10, v11);
            }
        }
        buf ^= 1;
    }

    // Epilogue: quad-reduce l once, normalize, write half output
    const int g = lane >> 2, t4 = lane & 3;
    float lA = l[0], lB = l[1];
    lA += __shfl_xor_sync(0xffffffffu, lA, 1);
    lA += __shfl_xor_sync(0xffffffffu, lA, 2);
    lB += __shfl_xor_sync(0xffffffffu, lB, 1);
    lB += __shfl_xor_sync(0xffffffffu, lB, 2);
    const float invA = 1.f / lA, invB = 1.f / lB;
    const int qg = b * SEQ + qt * 64 + w * 16 + g;
    #pragma unroll
    for (int ni = 0; ni < 8; ni++) {
        int c = h * 64 + ni * 8 + 2 * t4;
        *(__half2*)(out + (size_t)qg * EMBED + c) =
            __floats2half2_rn(ov[ni][0] * invA, ov[ni][1] * invA);
        *(__half2*)(out + (size_t)(qg + 8) * EMBED + c) =
            __floats2half2_rn(ov[ni][2] * invB, ov[ni][3] * invB);
    }
}

// ===========================================================================
// Host launcher
// ===========================================================================
extern "C" void kernel_launch(void* const* d_in, const int* in_sizes, int n_in,
                              void* d_out, int out_size) {
    const float* x      = (const float*)d_in[0];
    const float* w_qkv  = (const float*)d_in[1];
    const float* w_proj = (const float*)d_in[2];
    const float* b_proj = (const float*)d_in[3];
    const float* w_fc1  = (const float*)d_in[4];
    const float* b_fc1  = (const float*)d_in[5];
    const float* w_fc2  = (const float*)d_in[6];
    const float* b_fc2  = (const float*)d_in[7];
    const float* g1     = (const float*)d_in[8];
    const float* be1    = (const float*)d_in[9];
    const float* g2     = (const float*)d_in[10];
    const float* be2    = (const float*)d_in[11];
    float* out = (float*)d_out;

    void* sp = nullptr;
    cudaGetSymbolAddress(&sp, g_scratch);
    float* scratch = (float*)sp;
    float*  s_x1    = scratch;
    __half* s_h     = (__half*)(scratch + 1ull * UNIT);
    __half* s_attn  = (__half*)(scratch + 2ull * UNIT);
    __half* s_qkv   = (__half*)(scratch + 3ull * UNIT);
    __half* s_mlp   = (__half*)(scratch + 5ull * UNIT);
    __half* wh_qkv  = (__half*)(scratch + 7ull * UNIT);
    __half* wh_proj = (__half*)(scratch + 8ull * UNIT);
    __half* wh_fc1  = (__half*)(scratch + 9ull * UNIT);
    __half* wh_fc2  = (__half*)(scratch + 10ull * UNIT);

    const int ATT_SMEM  = 320 * PA * (int)sizeof(__half);    // 46080
    const int GEMM_SMEM = 2 * STAGE_H * (int)sizeof(__half); // 71680
    cudaFuncSetAttribute(attn_mma, cudaFuncAttributeMaxDynamicSharedMemorySize, ATT_SMEM);
    cudaFuncSetAttribute(hmma_gemm<0,0,0,1>, cudaFuncAttributeMaxDynamicSharedMemorySize, GEMM_SMEM);
    cudaFuncSetAttribute(hmma_gemm<1,0,1,0>, cudaFuncAttributeMaxDynamicSharedMemorySize, GEMM_SMEM);
    cudaFuncSetAttribute(hmma_gemm<1,1,0,1>, cudaFuncAttributeMaxDynamicSharedMemorySize, GEMM_SMEM);

    dim3 t256(256), t128(128);

    // 0. All weight conversions -> half [K,N] (natural layout), one launch
    conv_all<<<(CONV_TOTAL / 16 + 255) / 256, t256>>>(
        w_qkv, wh_qkv, w_proj, wh_proj, w_fc1, wh_fc1, w_fc2, wh_fc2);

    // 1. LN1 -> half
    ln_kernel<<<MROWS, t256>>>(x, g1, be1, s_h);

    // 2. QKV = h @ w_qkv  -> half
    hmma_gemm<0,0,0,1><<<dim3(3072/TN, MROWS/TM), t128, GEMM_SMEM>>>(
        s_h, wh_qkv, nullptr, nullptr, s_qkv, 3072, 1024);

    // 3. Attention -> half (query tile 64, f16-acc QK, 4 CTAs/SM)
    attn_mma<<<dim3(SEQ / 64, BATCH * NHEAD), t128, ATT_SMEM>>>(s_qkv, s_attn);

    // 4. x1 = x + attn @ w_proj + b_proj  -> float
    hmma_gemm<1,0,1,0><<<dim3(1024/TN, MROWS/TM), t128, GEMM_SMEM>>>(
        s_attn, wh_proj, b_proj, x, s_x1, 1024, 1024);

    // 5. LN2 -> half
    ln_kernel<<<MROWS, t256>>>(s_x1, g2, be2, s_h);

    // 6. mlp = gelu(h2 @ w_fc1 + b_fc1) -> half
    hmma_gemm<1,1,0,1><<<dim3(4096/TN, MROWS/TM), t128, GEMM_SMEM>>>(
        s_h, wh_fc1, b_fc1, nullptr, s_mlp, 4096, 1024);

    // 7. out = x1 + mlp @ w_fc2 + b_fc2  -> float
    hmma_gemm<1,0,1,0><<<dim3(1024/TN, MROWS/TM), t128, GEMM_SMEM>>>(
        s_mlp, wh_fc2, b_fc2, s_x1, out, 1024, 4096);
}